// round 9
// baseline (speedup 1.0000x reference)
#include <cuda_runtime.h>

// logLikelihood_loss: sum over (B,T,P) of -log(clip(bivariate_gaussian_pdf, 1e-10)) / P
// B=64, T=128, P=512 -> 4,194,304 elements. y_target: (...,3) f32, o_pred: (...,5) f32.
// HBM-bound streaming reduction. Log-domain formulation avoids exp/log round-trip.
//
// R7: revert to the R1 compute structure (one 4-record group per thread, 4096
//     blocks, plain float4 loads). R5/R6 grid-stride variants regressed to
//     ~29us because the loop serializes each warp's 8-LDG burst behind the
//     previous iteration's compute (shared data registers + guard branch) --
//     R1's front-loaded all-warps burst is what fed DRAM to 74%. Keep only the
//     validated single-launch last-block reduction (rel_err 0.0) to remove the
//     ~3us zero-kernel + second-launch overhead from R1's total.

#define N_ELEM   4194304
#define GROUPS   (N_ELEM / 4)        // 4 records per thread
#define THREADS  256
#define BLOCKS   (GROUPS / THREADS)  // 4096

__device__ float        g_partials[BLOCKS];
__device__ unsigned int g_count = 0;   // atomicInc wraps to 0 -> graph-replay-safe

// Accurate tanh from fast exp (independent of -use_fast_math's tanh.approx,
// whose abs error would poison 1-rho^2).
__device__ __forceinline__ float fast_tanh(float x) {
    float ax = fabsf(x);
    float e  = __expf(2.0f * ax);
    float t  = 1.0f - __fdividef(2.0f, e + 1.0f);
    return copysignf(t, x);
}

__global__ __launch_bounds__(THREADS)
void nll_kernel(const float* __restrict__ y, const float* __restrict__ o,
                float* __restrict__ out) {
    const int g = blockIdx.x * blockDim.x + threadIdx.x;   // group of 4 records

    // Direct AoS loads: 5 float4 from o_pred, 3 float4 from y_target.
    // All 8 LDG.128 issue up front -> full-chip burst keeps DRAM saturated.
    const float4* o4 = reinterpret_cast<const float4*>(o) + (size_t)g * 5;
    const float4* y4 = reinterpret_cast<const float4*>(y) + (size_t)g * 3;

    float of[20], yf[12];
#pragma unroll
    for (int k = 0; k < 5; k++) reinterpret_cast<float4*>(of)[k] = o4[k];
#pragma unroll
    for (int k = 0; k < 3; k++) reinterpret_cast<float4*>(yf)[k] = y4[k];

    const float LOG_2PI  = 1.8378770664093453f;   // ln(2*pi)
    const float CLAMP_HI = 23.025850929940457f;   // -ln(1e-10)

    float acc = 0.0f;
#pragma unroll
    for (int j = 0; j < 4; j++) {
        float mux = of[5 * j + 0];
        float muy = of[5 * j + 1];
        float lsx = of[5 * j + 2];   // log(sx)
        float lsy = of[5 * j + 3];   // log(sy)
        float cra = of[5 * j + 4];   // pre-tanh corr

        float y1 = yf[3 * j + 1];
        float y2 = yf[3 * j + 2];

        float inv_sx = __expf(-lsx);
        float inv_sy = __expf(-lsy);
        float nx = (y1 - mux) * inv_sx;
        float ny = (y2 - muy) * inv_sy;

        float tt = fast_tanh(cra);
        float om = fmaf(-tt, tt, 1.0f);            // 1 - rho^2 > 0
        float z  = fmaf(nx, nx, fmaf(ny, ny, -2.0f * tt * nx * ny));

        // -log pdf = z/(2*om) + log(2pi) + log(sx) + log(sy) + 0.5*log(om)
        float nll = 0.5f * __fdividef(z, om)
                  + (LOG_2PI + lsx + lsy + 0.5f * __logf(om));
        acc += fminf(nll, CLAMP_HI);               // == -log(clip(pdf, 1e-10))
    }

    // ── Block reduction ───────────────────────────────────────────────────
#pragma unroll
    for (int off = 16; off; off >>= 1)
        acc += __shfl_down_sync(0xffffffffu, acc, off);

    __shared__ float wsum[THREADS / 32];
    __shared__ int   s_last;
    const int lane = threadIdx.x & 31;
    const int wid  = threadIdx.x >> 5;
    if (lane == 0) wsum[wid] = acc;
    __syncthreads();

    if (wid == 0) {
        float v = (lane < THREADS / 32) ? wsum[lane] : 0.0f;
#pragma unroll
        for (int off = 4; off; off >>= 1)
            v += __shfl_down_sync(0xffffffffu, v, off);
        if (lane == 0) {
            g_partials[blockIdx.x] = v;
            __threadfence();
            unsigned old = atomicInc(&g_count, BLOCKS - 1);  // wraps -> replay-safe
            s_last = (old == BLOCKS - 1);
        }
    }
    __syncthreads();

    // ── Last block: final reduction over 4096 partials (L2-resident) ──────
    if (s_last) {
        __threadfence();
        float v = 0.0f;
#pragma unroll
        for (int k = 0; k < BLOCKS / THREADS; k++)
            v += __ldcg(&g_partials[threadIdx.x + k * THREADS]);  // bypass L1

#pragma unroll
        for (int off = 16; off; off >>= 1)
            v += __shfl_down_sync(0xffffffffu, v, off);
        if (lane == 0) wsum[wid] = v;
        __syncthreads();
        if (wid == 0) {
            float s = (lane < THREADS / 32) ? wsum[lane] : 0.0f;
#pragma unroll
            for (int off = 4; off; off >>= 1)
                s += __shfl_down_sync(0xffffffffu, s, off);
            if (lane == 0)
                out[0] = s * (1.0f / 512.0f);   // divide by P once
        }
    }
}

extern "C" void kernel_launch(void* const* d_in, const int* in_sizes, int n_in,
                              void* d_out, int out_size) {
    const float* y = (const float*)d_in[0];   // y_target, 12,582,912 floats
    const float* o = (const float*)d_in[1];   // o_pred,  20,971,520 floats
    float* out = (float*)d_out;               // scalar fp32

    nll_kernel<<<BLOCKS, THREADS>>>(y, o, out);
}

// round 10
// speedup vs baseline: 1.1595x; 1.1595x over previous
#include <cuda_runtime.h>

// logLikelihood_loss: sum over (B,T,P) of -log(clip(bivariate_gaussian_pdf, 1e-10)) / P
// B=64, T=128, P=512 -> 4,194,304 elements. y_target: (...,3) f32, o_pred: (...,5) f32.
// HBM-bound streaming reduction. Log-domain formulation avoids exp/log round-trip.
//
// R9: R7's last-block tail cost 8us / 19 DRAM points: its per-block
//     __threadfence() (gpu scope) emits CCTL.IVALL -> 4096 full L1D
//     invalidates stalling L1tex under the streaming loads. Replace with
//     fence-free scoped atomics: red.relaxed.gpu.add.f32 into g_sum, then
//     atom.acq_rel.gpu.inc.u32 on g_count (release half orders the RED, no L1
//     flush). Final block reads g_sum via relaxed atomic RMW (L2-coherent),
//     writes out[0], resets g_sum -> single launch, graph-replay-safe.

#define N_ELEM   4194304
#define GROUPS   (N_ELEM / 4)        // 4 records per thread
#define THREADS  256
#define BLOCKS   (GROUPS / THREADS)  // 4096

__device__ float        g_sum   = 0.0f;  // reset by last block each run
__device__ unsigned int g_count = 0;     // atom.inc wraps to 0 -> replay-safe

// Accurate tanh from fast exp (independent of -use_fast_math's tanh.approx,
// whose abs error would poison 1-rho^2).
__device__ __forceinline__ float fast_tanh(float x) {
    float ax = fabsf(x);
    float e  = __expf(2.0f * ax);
    float t  = 1.0f - __fdividef(2.0f, e + 1.0f);
    return copysignf(t, x);
}

__global__ __launch_bounds__(THREADS)
void nll_kernel(const float* __restrict__ y, const float* __restrict__ o,
                float* __restrict__ out) {
    const int g = blockIdx.x * blockDim.x + threadIdx.x;   // group of 4 records

    // Direct AoS loads: 5 float4 from o_pred, 3 float4 from y_target.
    // All 8 LDG.128 issue up front -> full-chip burst keeps DRAM saturated.
    const float4* o4 = reinterpret_cast<const float4*>(o) + (size_t)g * 5;
    const float4* y4 = reinterpret_cast<const float4*>(y) + (size_t)g * 3;

    float of[20], yf[12];
#pragma unroll
    for (int k = 0; k < 5; k++) reinterpret_cast<float4*>(of)[k] = o4[k];
#pragma unroll
    for (int k = 0; k < 3; k++) reinterpret_cast<float4*>(yf)[k] = y4[k];

    const float LOG_2PI  = 1.8378770664093453f;   // ln(2*pi)
    const float CLAMP_HI = 23.025850929940457f;   // -ln(1e-10)

    float acc = 0.0f;
#pragma unroll
    for (int j = 0; j < 4; j++) {
        float mux = of[5 * j + 0];
        float muy = of[5 * j + 1];
        float lsx = of[5 * j + 2];   // log(sx)
        float lsy = of[5 * j + 3];   // log(sy)
        float cra = of[5 * j + 4];   // pre-tanh corr

        float y1 = yf[3 * j + 1];
        float y2 = yf[3 * j + 2];

        float inv_sx = __expf(-lsx);
        float inv_sy = __expf(-lsy);
        float nx = (y1 - mux) * inv_sx;
        float ny = (y2 - muy) * inv_sy;

        float tt = fast_tanh(cra);
        float om = fmaf(-tt, tt, 1.0f);            // 1 - rho^2 > 0
        float z  = fmaf(nx, nx, fmaf(ny, ny, -2.0f * tt * nx * ny));

        // -log pdf = z/(2*om) + log(2pi) + log(sx) + log(sy) + 0.5*log(om)
        float nll = 0.5f * __fdividef(z, om)
                  + (LOG_2PI + lsx + lsy + 0.5f * __logf(om));
        acc += fminf(nll, CLAMP_HI);               // == -log(clip(pdf, 1e-10))
    }

    // ── Block reduction (identical to R1) ─────────────────────────────────
#pragma unroll
    for (int off = 16; off; off >>= 1)
        acc += __shfl_down_sync(0xffffffffu, acc, off);

    __shared__ float wsum[THREADS / 32];
    const int lane = threadIdx.x & 31;
    const int wid  = threadIdx.x >> 5;
    if (lane == 0) wsum[wid] = acc;
    __syncthreads();

    if (wid == 0) {
        float v = (lane < THREADS / 32) ? wsum[lane] : 0.0f;
#pragma unroll
        for (int off = 4; off; off >>= 1)
            v += __shfl_down_sync(0xffffffffu, v, off);

        if (lane == 0) {
            float val = v * (1.0f / 512.0f);      // fold /P here
            float* gs = &g_sum;
            unsigned* gc = &g_count;

            // Relaxed RED into the device accumulator (performed at L2).
            asm volatile("red.relaxed.gpu.global.add.f32 [%0], %1;"
                         :: "l"(gs), "f"(val) : "memory");
            // acq_rel inc: release half orders the RED above before the inc,
            // WITHOUT a gpu-scope fence (no CCTL.IVALL / L1 invalidate).
            unsigned old;
            asm volatile("atom.acq_rel.gpu.global.inc.u32 %0, [%1], %2;"
                         : "=r"(old) : "l"(gc), "r"((unsigned)(BLOCKS - 1))
                         : "memory");

            if (old == BLOCKS - 1) {
                // All 4096 REDs to g_sum are ordered before their incs; a
                // relaxed atomic RMW on the same address at L2 sees them all.
                float s;
                asm volatile("atom.relaxed.gpu.global.add.f32 %0, [%1], %2;"
                             : "=f"(s) : "l"(gs), "f"(0.0f) : "memory");
                out[0] = s;
                // Reset accumulator for the next graph replay.
                asm volatile("st.relaxed.gpu.global.f32 [%0], %1;"
                             :: "l"(gs), "f"(0.0f) : "memory");
            }
        }
    }
}

extern "C" void kernel_launch(void* const* d_in, const int* in_sizes, int n_in,
                              void* d_out, int out_size) {
    const float* y = (const float*)d_in[0];   // y_target, 12,582,912 floats
    const float* o = (const float*)d_in[1];   // o_pred,  20,971,520 floats
    float* out = (float*)d_out;               // scalar fp32

    nll_kernel<<<BLOCKS, THREADS>>>(y, o, out);
}

// round 12
// speedup vs baseline: 1.3270x; 1.1445x over previous
#include <cuda_runtime.h>

// logLikelihood_loss: sum over (B,T,P) of -log(clip(bivariate_gaussian_pdf, 1e-10)) / P
// B=64, T=128, P=512 -> 4,194,304 elements. y_target: (...,3) f32, o_pred: (...,5) f32.
// HBM-bound streaming reduction. Log-domain formulation avoids exp/log round-trip.
//
// R10: R9's atom.acq_rel.gpu still invalidated L1 (acquire half) 4096 times ->
//      DRAM stuck at 63%. New tail: pack {count:12 | biased Q32 sum:52} into ONE
//      u64 and use a single RELAXED atomicAdd per block. Per-location atomicity
//      makes the 4096th block's returned 'old' contain every other block's
//      contribution -- no second location to read, so no acquire, no fence, no
//      L1 invalidate anywhere. Winner unpacks, writes out[0], atomicExch-resets
//      the word to 0 (kernel boundary orders it for the next graph replay).
//      Compute section byte-identical to R1 (23.6us kernel, DRAM 74%).

#define N_ELEM   4194304
#define GROUPS   (N_ELEM / 4)        // 4 records per thread
#define THREADS  256
#define BLOCKS   (GROUPS / THREADS)  // 4096

// Fixed-point packing: bits [0:52) = (v + BIAS) * 2^32, bits [52:64) = count.
// Range: 4096 blocks * (|v|<=46 + BIAS 64) * 2^32 < 2^52. Per-block v is the
// block sum / 512 (|v| <~ 46); BIAS keeps the field positive.
#define PACK_BIAS   64.0
#define PACK_SCALE  4294967296.0     // 2^32
#define SUM_MASK    ((1ULL << 52) - 1)

__device__ unsigned long long g_pack = 0ULL;   // reset by winning block

// Accurate tanh from fast exp (independent of -use_fast_math's tanh.approx,
// whose abs error would poison 1-rho^2).
__device__ __forceinline__ float fast_tanh(float x) {
    float ax = fabsf(x);
    float e  = __expf(2.0f * ax);
    float t  = 1.0f - __fdividef(2.0f, e + 1.0f);
    return copysignf(t, x);
}

__global__ __launch_bounds__(THREADS)
void nll_kernel(const float* __restrict__ y, const float* __restrict__ o,
                float* __restrict__ out) {
    const int g = blockIdx.x * blockDim.x + threadIdx.x;   // group of 4 records

    // Direct AoS loads: 5 float4 from o_pred, 3 float4 from y_target.
    // All 8 LDG.128 issue up front -> full-chip burst keeps DRAM saturated.
    const float4* o4 = reinterpret_cast<const float4*>(o) + (size_t)g * 5;
    const float4* y4 = reinterpret_cast<const float4*>(y) + (size_t)g * 3;

    float of[20], yf[12];
#pragma unroll
    for (int k = 0; k < 5; k++) reinterpret_cast<float4*>(of)[k] = o4[k];
#pragma unroll
    for (int k = 0; k < 3; k++) reinterpret_cast<float4*>(yf)[k] = y4[k];

    const float LOG_2PI  = 1.8378770664093453f;   // ln(2*pi)
    const float CLAMP_HI = 23.025850929940457f;   // -ln(1e-10)

    float acc = 0.0f;
#pragma unroll
    for (int j = 0; j < 4; j++) {
        float mux = of[5 * j + 0];
        float muy = of[5 * j + 1];
        float lsx = of[5 * j + 2];   // log(sx)
        float lsy = of[5 * j + 3];   // log(sy)
        float cra = of[5 * j + 4];   // pre-tanh corr

        float y1 = yf[3 * j + 1];
        float y2 = yf[3 * j + 2];

        float inv_sx = __expf(-lsx);
        float inv_sy = __expf(-lsy);
        float nx = (y1 - mux) * inv_sx;
        float ny = (y2 - muy) * inv_sy;

        float tt = fast_tanh(cra);
        float om = fmaf(-tt, tt, 1.0f);            // 1 - rho^2 > 0
        float z  = fmaf(nx, nx, fmaf(ny, ny, -2.0f * tt * nx * ny));

        // -log pdf = z/(2*om) + log(2pi) + log(sx) + log(sy) + 0.5*log(om)
        float nll = 0.5f * __fdividef(z, om)
                  + (LOG_2PI + lsx + lsy + 0.5f * __logf(om));
        acc += fminf(nll, CLAMP_HI);               // == -log(clip(pdf, 1e-10))
    }

    // ── Block reduction (identical to R1) ─────────────────────────────────
#pragma unroll
    for (int off = 16; off; off >>= 1)
        acc += __shfl_down_sync(0xffffffffu, acc, off);

    __shared__ float wsum[THREADS / 32];
    const int lane = threadIdx.x & 31;
    const int wid  = threadIdx.x >> 5;
    if (lane == 0) wsum[wid] = acc;
    __syncthreads();

    if (wid == 0) {
        float v = (lane < THREADS / 32) ? wsum[lane] : 0.0f;
#pragma unroll
        for (int off = 4; off; off >>= 1)
            v += __shfl_down_sync(0xffffffffu, v, off);

        if (lane == 0) {
            // Fold /P, then pack {count=1, biased Q32 sum} and add atomically.
            double vb = (double)(v * (1.0f / 512.0f)) + PACK_BIAS;
            unsigned long long pack =
                (1ULL << 52) | (unsigned long long)llrint(vb * PACK_SCALE);
            unsigned long long old = atomicAdd(&g_pack, pack);   // relaxed RMW

            if ((old >> 52) == (unsigned long long)(BLOCKS - 1)) {
                // 'old + pack' holds every block's contribution (same word).
                unsigned long long total = (old + pack) & SUM_MASK;
                double s = (double)total * (1.0 / PACK_SCALE)
                         - PACK_BIAS * (double)BLOCKS;
                out[0] = (float)s;
                atomicExch(&g_pack, 0ULL);   // reset for next graph replay
            }
        }
    }
}

extern "C" void kernel_launch(void* const* d_in, const int* in_sizes, int n_in,
                              void* d_out, int out_size) {
    const float* y = (const float*)d_in[0];   // y_target, 12,582,912 floats
    const float* o = (const float*)d_in[1];   // o_pred,  20,971,520 floats
    float* out = (float*)d_out;               // scalar fp32

    nll_kernel<<<BLOCKS, THREADS>>>(y, o, out);
}